// round 1
// baseline (speedup 1.0000x reference)
#include <cuda_runtime.h>
#include <cuda_bf16.h>
#include <cstdint>

// Problem constants
#define BATCH   512
#define CIN     128
#define LIN     1024
#define KW      5
#define LOUT    1020      // LIN - KW + 1
#define TSEQ    1020      // sequence length after reshape: 128*1020/128
#define H1      32
#define H2      16
#define H3      32
#define MROWS   (BATCH * TSEQ)   // 522240

// ---------------- scratch (device globals: no runtime allocation) ----------------
__device__ float g_conv[(size_t)BATCH * CIN * LOUT];     // also the seq matrix [M,128]
__device__ float g_xg1 [(size_t)MROWS * 4 * H1];         // [M,128]
__device__ float g_h1  [(size_t)MROWS * H1];             // [M,32]
__device__ float g_xg2 [(size_t)MROWS * 4 * H2];         // [M,64]
__device__ float g_h2  [(size_t)MROWS * H2];             // [M,16]
__device__ float g_xg3 [(size_t)MROWS * 4 * H3];         // [M,128]

// ---------------- math helpers ----------------
__device__ __forceinline__ float sigmoidf_(float x) {
    x = fminf(30.f, fmaxf(-30.f, x));
    return __fdividef(1.f, 1.f + __expf(-x));
}
__device__ __forceinline__ float tanhf_(float x) {
    x = fminf(15.f, fmaxf(-15.f, x));
    float e = __expf(2.f * x);
    return __fdividef(e - 1.f, e + 1.f);
}

// ---------------- conv1d: out[b,co,l] = bias[co] + sum_{ci,k} x[b,ci,l+k]*w[co,ci,k]
// grid (16, 512), block 256. Tile: 128 co x 64 l per CTA, 8x4 per thread.
__global__ __launch_bounds__(256) void conv_kernel(
    const float* __restrict__ x, const float* __restrict__ w, const float* __restrict__ bias)
{
    __shared__ __align__(16) float xs[8][72];      // 8 ci x (64+4) window
    __shared__ float ws[8][5][128];                // [ci][k][co]

    const int b   = blockIdx.y;
    const int lb  = blockIdx.x * 64;
    const int tid = threadIdx.x;
    const int txl = tid & 15;     // l group
    const int tyc = tid >> 4;     // co group

    float acc[8][4];
#pragma unroll
    for (int i = 0; i < 8; i++)
#pragma unroll
        for (int j = 0; j < 4; j++) acc[i][j] = 0.f;

    const float* xb = x + (size_t)b * (CIN * LIN);

    for (int ci0 = 0; ci0 < CIN; ci0 += 8) {
        __syncthreads();
        for (int idx = tid; idx < 8 * 68; idx += 256) {
            int ci = idx / 68, p = idx - ci * 68;
            int l = lb + p;
            xs[ci][p] = (l < LIN) ? xb[(size_t)(ci0 + ci) * LIN + l] : 0.f;
        }
        for (int idx = tid; idx < 8 * 5 * 128; idx += 256) {
            int ci = idx / 640, rem = idx - ci * 640;
            int k = rem >> 7, co = rem & 127;
            ws[ci][k][co] = w[((size_t)co * CIN + (ci0 + ci)) * KW + k];
        }
        __syncthreads();

#pragma unroll
        for (int ci = 0; ci < 8; ci++) {
            float xr[8];
#pragma unroll
            for (int p = 0; p < 8; p++) xr[p] = xs[ci][txl * 4 + p];
#pragma unroll
            for (int k = 0; k < 5; k++) {
                float wv[8];
#pragma unroll
                for (int i = 0; i < 8; i++) wv[i] = ws[ci][k][tyc + 16 * i];
#pragma unroll
                for (int i = 0; i < 8; i++)
#pragma unroll
                    for (int j = 0; j < 4; j++)
                        acc[i][j] = fmaf(wv[i], xr[j + k], acc[i][j]);
            }
        }
    }

    float* ob = g_conv + (size_t)b * (CIN * LOUT);
#pragma unroll
    for (int i = 0; i < 8; i++) {
        int co = tyc + 16 * i;
        float bv = bias[co];
#pragma unroll
        for (int j = 0; j < 4; j++) {
            int l = lb + txl * 4 + j;
            if (l < LOUT) ob[(size_t)co * LOUT + l] = acc[i][j] + bv;
        }
    }
}

// ---------------- generic C[M,Ncols] = A[M,K] @ W[Nrows,K]^T + b1[n] + b2[n]
// grid (M/64, Ncols/64), block 256, 4x4 register tile.
template<int K>
__global__ __launch_bounds__(256) void gemm_bias_kernel(
    const float* __restrict__ A, const float* __restrict__ W,
    const float* __restrict__ b1, const float* __restrict__ b2,
    float* __restrict__ C, int Ncols)
{
    constexpr int KC = (K < 64) ? K : 64;
    __shared__ float As[64][KC + 1];
    __shared__ float Ws[64][KC + 1];

    const int row0 = blockIdx.x * 64;
    const int n0   = blockIdx.y * 64;
    const int tid  = threadIdx.x;
    const int tx   = tid & 15;
    const int ty   = tid >> 4;

    float acc[4][4];
#pragma unroll
    for (int i = 0; i < 4; i++)
#pragma unroll
        for (int j = 0; j < 4; j++) acc[i][j] = 0.f;

    for (int k0 = 0; k0 < K; k0 += KC) {
        __syncthreads();
        for (int idx = tid; idx < 64 * KC; idx += 256) {
            int r = idx / KC, k = idx - r * KC;
            As[r][k] = A[(size_t)(row0 + r) * K + k0 + k];
            Ws[r][k] = W[(size_t)(n0 + r) * K + k0 + k];
        }
        __syncthreads();
#pragma unroll
        for (int k = 0; k < KC; k++) {
            float av[4], wv[4];
#pragma unroll
            for (int i = 0; i < 4; i++) av[i] = As[16 * i + ty][k];
#pragma unroll
            for (int j = 0; j < 4; j++) wv[j] = Ws[16 * j + tx][k];
#pragma unroll
            for (int i = 0; i < 4; i++)
#pragma unroll
                for (int j = 0; j < 4; j++)
                    acc[i][j] = fmaf(av[i], wv[j], acc[i][j]);
        }
    }

    float bv[4];
#pragma unroll
    for (int j = 0; j < 4; j++) {
        int n = n0 + 16 * j + tx;
        bv[j] = b1[n] + b2[n];
    }
#pragma unroll
    for (int i = 0; i < 4; i++) {
        size_t rbase = (size_t)(row0 + 16 * i + ty) * Ncols;
#pragma unroll
        for (int j = 0; j < 4; j++)
            C[rbase + n0 + 16 * j + tx] = acc[i][j] + bv[j];
    }
}

// ---------------- LSTM recurrence: warp per batch, Whh in registers.
// xg: [B, T, 4H] precomputed input gates (+both biases).
// hout: WRITE_SEQ ? [B,T,H] all h : [B,H] final h only.
template<int H, bool WRITE_SEQ>
__global__ __launch_bounds__(128, 1) void lstm_kernel(
    const float* __restrict__ xg, const float* __restrict__ whh,
    float* __restrict__ hout)
{
    const int tid = threadIdx.x;
    const int wp  = tid >> 5;
    const int j   = tid & 31;
    const int b   = blockIdx.x * 4 + wp;

    __shared__ float hs[4][H];

    float wr[4][H];
    if (j < H) {
#pragma unroll
        for (int g = 0; g < 4; g++)
#pragma unroll
            for (int k = 0; k < H; k++)
                wr[g][k] = whh[(size_t)(g * H + j) * H + k];
    }

    float h = 0.f, c = 0.f;
    if (j < H) hs[wp][j] = 0.f;
    __syncwarp();

    const float* xgb = xg + (size_t)b * TSEQ * (4 * H);
    float* hob = WRITE_SEQ ? (hout + (size_t)b * TSEQ * H) : (hout + (size_t)b * H);

    for (int t = 0; t < TSEQ; t++) {
        if (j < H) {
            const float* xt = xgb + (size_t)t * (4 * H);
            float a0 = xt[0 * H + j];
            float a1 = xt[1 * H + j];
            float a2 = xt[2 * H + j];
            float a3 = xt[3 * H + j];
#pragma unroll
            for (int k = 0; k < H; k++) {
                float hk = hs[wp][k];
                a0 = fmaf(hk, wr[0][k], a0);
                a1 = fmaf(hk, wr[1][k], a1);
                a2 = fmaf(hk, wr[2][k], a2);
                a3 = fmaf(hk, wr[3][k], a3);
            }
            float ig = sigmoidf_(a0);
            float fg = sigmoidf_(a1);
            float gg = tanhf_(a2);
            float og = sigmoidf_(a3);
            c = fg * c + ig * gg;
            h = og * tanhf_(c);
            if (WRITE_SEQ) hob[(size_t)t * H + j] = h;
        }
        __syncwarp();
        if (j < H) hs[wp][j] = h;
        __syncwarp();
    }
    if (!WRITE_SEQ && j < H) hob[j] = h;
}

// ---------------- launch ----------------
extern "C" void kernel_launch(void* const* d_in, const int* in_sizes, int n_in,
                              void* d_out, int out_size)
{
    const float* x      = (const float*)d_in[0];
    const float* conv_w = (const float*)d_in[1];
    const float* conv_b = (const float*)d_in[2];
    const float* Wih1   = (const float*)d_in[3];
    const float* Whh1   = (const float*)d_in[4];
    const float* bih1   = (const float*)d_in[5];
    const float* bhh1   = (const float*)d_in[6];
    const float* Wih2   = (const float*)d_in[7];
    const float* Whh2   = (const float*)d_in[8];
    const float* bih2   = (const float*)d_in[9];
    const float* bhh2   = (const float*)d_in[10];
    const float* Wih3   = (const float*)d_in[11];
    const float* Whh3   = (const float*)d_in[12];
    const float* bih3   = (const float*)d_in[13];
    const float* bhh3   = (const float*)d_in[14];
    float* out = (float*)d_out;

    float *conv_p, *xg1_p, *h1_p, *xg2_p, *h2_p, *xg3_p;
    cudaGetSymbolAddress((void**)&conv_p, g_conv);
    cudaGetSymbolAddress((void**)&xg1_p,  g_xg1);
    cudaGetSymbolAddress((void**)&h1_p,   g_h1);
    cudaGetSymbolAddress((void**)&xg2_p,  g_xg2);
    cudaGetSymbolAddress((void**)&h2_p,   g_h2);
    cudaGetSymbolAddress((void**)&xg3_p,  g_xg3);

    // 1) conv -> g_conv  (doubles as seq matrix [M,128])
    conv_kernel<<<dim3(16, BATCH), 256>>>(x, conv_w, conv_b);

    // 2) xg1 = seq @ Wih1^T + bih1 + bhh1   [M,128]
    gemm_bias_kernel<128><<<dim3(MROWS / 64, 2), 256>>>(conv_p, Wih1, bih1, bhh1, xg1_p, 4 * H1);

    // 3) LSTM1 -> h1 [M,32]
    lstm_kernel<H1, true><<<BATCH / 4, 128>>>(xg1_p, Whh1, h1_p);

    // 4) xg2 = h1 @ Wih2^T + biases   [M,64]
    gemm_bias_kernel<32><<<dim3(MROWS / 64, 1), 256>>>(h1_p, Wih2, bih2, bhh2, xg2_p, 4 * H2);

    // 5) LSTM2 -> h2 [M,16]
    lstm_kernel<H2, true><<<BATCH / 4, 128>>>(xg2_p, Whh2, h2_p);

    // 6) xg3 = h2 @ Wih3^T + biases   [M,128]
    gemm_bias_kernel<16><<<dim3(MROWS / 64, 2), 256>>>(h2_p, Wih3, bih3, bhh3, xg3_p, 4 * H3);

    // 7) LSTM3 -> final h only -> d_out [512,32]
    lstm_kernel<H3, false><<<BATCH / 4, 128>>>(xg3_p, Whh3, out);

    (void)in_sizes; (void)n_in; (void)out_size;
}

// round 2
// speedup vs baseline: 2.4243x; 2.4243x over previous
#include <cuda_runtime.h>
#include <cuda_bf16.h>
#include <cstdint>

// Problem constants
#define BATCH   512
#define CIN     128
#define LIN     1024
#define KW      5
#define LOUT    1020
#define TSEQ    1020
#define H1      32
#define H2      16
#define H3      32
#define MROWS   (BATCH * TSEQ)   // 522240

// ---------------- scratch ----------------
__device__ float g_conv[(size_t)BATCH * CIN * LOUT];     // [B][128][1020]; also seq matrix [M,128]
__device__ float g_xg1 [(size_t)MROWS * 4 * H1];
__device__ float g_h1  [(size_t)MROWS * H1];
__device__ float g_xg2 [(size_t)MROWS * 4 * H2];
__device__ float g_h2  [(size_t)MROWS * H2];
__device__ float g_xg3 [(size_t)MROWS * 4 * H3];

// ---------------- helpers ----------------
__device__ __forceinline__ float sigmoidf_(float x) {
    x = fminf(30.f, fmaxf(-30.f, x));
    return __fdividef(1.f, 1.f + __expf(-x));
}
__device__ __forceinline__ float tanhf_(float x) {
    x = fminf(15.f, fmaxf(-15.f, x));
    float e = __expf(2.f * x);
    return __fdividef(e - 1.f, e + 1.f);
}
__device__ __forceinline__ uint32_t f2tf32(float f) {
    uint32_t r;
    asm("cvt.rna.tf32.f32 %0, %1;" : "=r"(r) : "f"(f));
    return r;
}
__device__ __forceinline__ void mma_tf32(float c[4], const uint32_t a[4], uint32_t b0, uint32_t b1) {
    asm volatile(
        "mma.sync.aligned.m16n8k8.row.col.f32.tf32.tf32.f32 "
        "{%0,%1,%2,%3}, {%4,%5,%6,%7}, {%8,%9}, {%0,%1,%2,%3};"
        : "+f"(c[0]), "+f"(c[1]), "+f"(c[2]), "+f"(c[3])
        : "r"(a[0]), "r"(a[1]), "r"(a[2]), "r"(a[3]), "r"(b0), "r"(b1));
}

// =====================================================================
// conv1d via tf32 MMA.  CTA tile: 128 co x 128 l.  grid (8, 512).
// K decomposed: 8 chunks of 16 ci, x 5 taps (shifted B reads).
// smem: Ws[5][128][20] (tf32) + Xs[16][136] (tf32)
// =====================================================================
#define CV_WS_STRIDE 20
#define CV_XS_STRIDE 136
#define CV_WS_ELEMS  (5 * 128 * CV_WS_STRIDE)          // 12800
#define CV_XS_ELEMS  (16 * CV_XS_STRIDE)               // 2176
#define CV_SMEM_BYTES ((CV_WS_ELEMS + CV_XS_ELEMS) * 4)  // 59904

__global__ __launch_bounds__(256) void conv_mma_kernel(
    const float* __restrict__ x, const float* __restrict__ w, const float* __restrict__ bias)
{
    extern __shared__ uint32_t smem_u[];
    uint32_t* Ws = smem_u;                 // [tap][co][cil] stride 20
    uint32_t* Xs = smem_u + CV_WS_ELEMS;   // [ci][p] stride 136

    const int b   = blockIdx.y;
    const int lb  = blockIdx.x * 128;
    const int tid = threadIdx.x;
    const int warp = tid >> 5;
    const int lane = tid & 31;
    const int g   = lane >> 2;
    const int t4  = lane & 3;
    const int warp_m = warp >> 1;   // 0..3 (32 co)
    const int warp_n = warp & 1;    // 0..1 (64 l)

    float acc[2][8][4];
#pragma unroll
    for (int mi = 0; mi < 2; mi++)
#pragma unroll
        for (int ni = 0; ni < 8; ni++)
#pragma unroll
            for (int e = 0; e < 4; e++) acc[mi][ni][e] = 0.f;

    const float* xb = x + (size_t)b * (CIN * LIN);

    for (int ci0 = 0; ci0 < CIN; ci0 += 16) {
        __syncthreads();
        // ---- load W chunk: [128co][16ci][5tap] -> Ws[tap][co][cil], tf32
        for (int v = tid; v < 2560; v += 256) {
            int co = v / 20;
            int r4 = v - co * 20;
            const float4 wv = *reinterpret_cast<const float4*>(w + (size_t)co * 640 + ci0 * 5 + r4 * 4);
            float we[4] = {wv.x, wv.y, wv.z, wv.w};
#pragma unroll
            for (int e = 0; e < 4; e++) {
                int r = r4 * 4 + e;
                int cil = r / 5;
                int tap = r - cil * 5;
                Ws[((tap * 128) + co) * CV_WS_STRIDE + cil] = f2tf32(we[e]);
            }
        }
        // ---- load X chunk: [16ci][132], tf32
        for (int v = tid; v < 16 * 33; v += 256) {
            int row = v / 33;
            int p4  = v - row * 33;
            const float* xr = xb + (size_t)(ci0 + row) * LIN;
            int gl = lb + p4 * 4;
            uint32_t o[4];
            if (gl + 3 < LIN) {
                float4 xv = *reinterpret_cast<const float4*>(xr + gl);
                o[0] = f2tf32(xv.x); o[1] = f2tf32(xv.y); o[2] = f2tf32(xv.z); o[3] = f2tf32(xv.w);
            } else {
#pragma unroll
                for (int e = 0; e < 4; e++)
                    o[e] = (gl + e < LIN) ? f2tf32(xr[gl + e]) : 0u;
            }
            *reinterpret_cast<uint4*>(&Xs[row * CV_XS_STRIDE + p4 * 4]) = make_uint4(o[0], o[1], o[2], o[3]);
        }
        __syncthreads();

#pragma unroll
        for (int tap = 0; tap < 5; tap++) {
#pragma unroll
            for (int ks = 0; ks < 2; ks++) {
                const int k0 = ks * 8;
                uint32_t a[2][4];
#pragma unroll
                for (int mi = 0; mi < 2; mi++) {
                    int row = warp_m * 32 + mi * 16;
                    const uint32_t* wsb = Ws + tap * 128 * CV_WS_STRIDE;
                    a[mi][0] = wsb[(row + g)     * CV_WS_STRIDE + k0 + t4];
                    a[mi][1] = wsb[(row + 8 + g) * CV_WS_STRIDE + k0 + t4];
                    a[mi][2] = wsb[(row + g)     * CV_WS_STRIDE + k0 + t4 + 4];
                    a[mi][3] = wsb[(row + 8 + g) * CV_WS_STRIDE + k0 + t4 + 4];
                }
#pragma unroll
                for (int ni = 0; ni < 8; ni++) {
                    int col = warp_n * 64 + ni * 8 + g + tap;
                    uint32_t b0 = Xs[(k0 + t4)     * CV_XS_STRIDE + col];
                    uint32_t b1 = Xs[(k0 + t4 + 4) * CV_XS_STRIDE + col];
                    mma_tf32(acc[0][ni], a[0], b0, b1);
                    mma_tf32(acc[1][ni], a[1], b0, b1);
                }
            }
        }
    }

    // ---- epilogue: + bias, store [co][l] layout
    float* ob = g_conv + (size_t)b * (CIN * LOUT);
#pragma unroll
    for (int mi = 0; mi < 2; mi++) {
        int row0 = warp_m * 32 + mi * 16 + g;
        float bv0 = bias[row0];
        float bv1 = bias[row0 + 8];
#pragma unroll
        for (int ni = 0; ni < 8; ni++) {
            int l = lb + warp_n * 64 + ni * 8 + 2 * t4;
            if (l + 1 < LOUT) {
                float2 v0 = make_float2(acc[mi][ni][0] + bv0, acc[mi][ni][1] + bv0);
                float2 v1 = make_float2(acc[mi][ni][2] + bv1, acc[mi][ni][3] + bv1);
                *reinterpret_cast<float2*>(ob + (size_t)row0 * LOUT + l) = v0;
                *reinterpret_cast<float2*>(ob + (size_t)(row0 + 8) * LOUT + l) = v1;
            } else if (l < LOUT) {
                ob[(size_t)row0 * LOUT + l]       = acc[mi][ni][0] + bv0;
                ob[(size_t)(row0 + 8) * LOUT + l] = acc[mi][ni][2] + bv1;
            }
        }
    }
}

// =====================================================================
// xg1 = seq[M,128] @ Wih1[128,128]^T + biases, tf32 MMA.
// CTA: 128 rows x 128 cols, full K=128 in smem. grid 4080.
// =====================================================================
#define XG_STRIDE 132
#define XG_SMEM_BYTES (2 * 128 * XG_STRIDE * 4)   // 135168

__global__ __launch_bounds__(256) void xg1_mma_kernel(
    const float* __restrict__ A, const float* __restrict__ W,
    const float* __restrict__ b1, const float* __restrict__ b2,
    float* __restrict__ C)
{
    extern __shared__ uint32_t smem_u[];
    uint32_t* As = smem_u;                    // [m][k] stride 132
    uint32_t* Bs = smem_u + 128 * XG_STRIDE;  // [n][k] stride 132

    const int row0 = blockIdx.x * 128;
    const int tid  = threadIdx.x;
    const int warp = tid >> 5;
    const int lane = tid & 31;
    const int g    = lane >> 2;
    const int t4   = lane & 3;
    const int warp_m = warp >> 1;
    const int warp_n = warp & 1;

    // load A tile + full W, tf32 converted
    for (int v = tid; v < 128 * 32; v += 256) {
        int r  = v >> 5;
        int k4 = (v & 31) * 4;
        float4 av = *reinterpret_cast<const float4*>(A + (size_t)(row0 + r) * 128 + k4);
        *reinterpret_cast<uint4*>(&As[r * XG_STRIDE + k4]) =
            make_uint4(f2tf32(av.x), f2tf32(av.y), f2tf32(av.z), f2tf32(av.w));
        float4 wv = *reinterpret_cast<const float4*>(W + (size_t)r * 128 + k4);
        *reinterpret_cast<uint4*>(&Bs[r * XG_STRIDE + k4]) =
            make_uint4(f2tf32(wv.x), f2tf32(wv.y), f2tf32(wv.z), f2tf32(wv.w));
    }
    __syncthreads();

    float acc[2][8][4];
#pragma unroll
    for (int mi = 0; mi < 2; mi++)
#pragma unroll
        for (int ni = 0; ni < 8; ni++)
#pragma unroll
            for (int e = 0; e < 4; e++) acc[mi][ni][e] = 0.f;

#pragma unroll
    for (int k0 = 0; k0 < 128; k0 += 8) {
        uint32_t a[2][4];
#pragma unroll
        for (int mi = 0; mi < 2; mi++) {
            int row = warp_m * 32 + mi * 16;
            a[mi][0] = As[(row + g)     * XG_STRIDE + k0 + t4];
            a[mi][1] = As[(row + 8 + g) * XG_STRIDE + k0 + t4];
            a[mi][2] = As[(row + g)     * XG_STRIDE + k0 + t4 + 4];
            a[mi][3] = As[(row + 8 + g) * XG_STRIDE + k0 + t4 + 4];
        }
#pragma unroll
        for (int ni = 0; ni < 8; ni++) {
            int n = warp_n * 64 + ni * 8 + g;
            uint32_t b0 = Bs[n * XG_STRIDE + k0 + t4];
            uint32_t b1 = Bs[n * XG_STRIDE + k0 + t4 + 4];
            mma_tf32(acc[0][ni], a[0], b0, b1);
            mma_tf32(acc[1][ni], a[1], b0, b1);
        }
    }

#pragma unroll
    for (int mi = 0; mi < 2; mi++) {
        int r0 = row0 + warp_m * 32 + mi * 16 + g;
#pragma unroll
        for (int ni = 0; ni < 8; ni++) {
            int n = warp_n * 64 + ni * 8 + 2 * t4;
            float bb0 = b1[n] + b2[n];
            float bb1 = b1[n + 1] + b2[n + 1];
            *reinterpret_cast<float2*>(C + (size_t)r0 * 128 + n) =
                make_float2(acc[mi][ni][0] + bb0, acc[mi][ni][1] + bb1);
            *reinterpret_cast<float2*>(C + (size_t)(r0 + 8) * 128 + n) =
                make_float2(acc[mi][ni][2] + bb0, acc[mi][ni][3] + bb1);
        }
    }
}

// =====================================================================
// scalar GEMM for small xg2/xg3
// =====================================================================
template<int K>
__global__ __launch_bounds__(256) void gemm_bias_kernel(
    const float* __restrict__ A, const float* __restrict__ W,
    const float* __restrict__ b1, const float* __restrict__ b2,
    float* __restrict__ C, int Ncols)
{
    constexpr int KC = (K < 64) ? K : 64;
    __shared__ float As[64][KC + 1];
    __shared__ float Ws2[64][KC + 1];

    const int row0 = blockIdx.x * 64;
    const int n0   = blockIdx.y * 64;
    const int tid  = threadIdx.x;
    const int tx   = tid & 15;
    const int ty   = tid >> 4;

    float acc[4][4];
#pragma unroll
    for (int i = 0; i < 4; i++)
#pragma unroll
        for (int j = 0; j < 4; j++) acc[i][j] = 0.f;

    for (int k0 = 0; k0 < K; k0 += KC) {
        __syncthreads();
        for (int idx = tid; idx < 64 * KC; idx += 256) {
            int r = idx / KC, k = idx - r * KC;
            As[r][k]  = A[(size_t)(row0 + r) * K + k0 + k];
            Ws2[r][k] = W[(size_t)(n0 + r) * K + k0 + k];
        }
        __syncthreads();
#pragma unroll
        for (int k = 0; k < KC; k++) {
            float av[4], wv[4];
#pragma unroll
            for (int i = 0; i < 4; i++) av[i] = As[16 * i + ty][k];
#pragma unroll
            for (int j = 0; j < 4; j++) wv[j] = Ws2[16 * j + tx][k];
#pragma unroll
            for (int i = 0; i < 4; i++)
#pragma unroll
                for (int j = 0; j < 4; j++)
                    acc[i][j] = fmaf(av[i], wv[j], acc[i][j]);
        }
    }

    float bv[4];
#pragma unroll
    for (int j = 0; j < 4; j++) {
        int n = n0 + 16 * j + tx;
        bv[j] = b1[n] + b2[n];
    }
#pragma unroll
    for (int i = 0; i < 4; i++) {
        size_t rbase = (size_t)(row0 + 16 * i + ty) * Ncols;
#pragma unroll
        for (int j = 0; j < 4; j++)
            C[rbase + n0 + 16 * j + tx] = acc[i][j] + bv[j];
    }
}

// =====================================================================
// LSTM recurrence: warp per batch, Whh in registers, xg[t+1] prefetched
// =====================================================================
template<int H, bool WRITE_SEQ>
__global__ __launch_bounds__(128, 1) void lstm_kernel(
    const float* __restrict__ xg, const float* __restrict__ whh,
    float* __restrict__ hout)
{
    const int tid = threadIdx.x;
    const int wp  = tid >> 5;
    const int j   = tid & 31;
    const int b   = blockIdx.x * 4 + wp;

    __shared__ float hs[4][H];

    float wr[4][H];
    if (j < H) {
#pragma unroll
        for (int gt = 0; gt < 4; gt++)
#pragma unroll
            for (int k = 0; k < H; k++)
                wr[gt][k] = whh[(size_t)(gt * H + j) * H + k];
    }

    float h = 0.f, c = 0.f;
    if (j < H) hs[wp][j] = 0.f;
    __syncwarp();

    const float* xgb = xg + (size_t)b * TSEQ * (4 * H);
    float* hob = WRITE_SEQ ? (hout + (size_t)b * TSEQ * H) : (hout + (size_t)b * H);

    float p0 = 0.f, p1 = 0.f, p2 = 0.f, p3 = 0.f;
    if (j < H) {
        p0 = xgb[0 * H + j]; p1 = xgb[1 * H + j];
        p2 = xgb[2 * H + j]; p3 = xgb[3 * H + j];
    }

    for (int t = 0; t < TSEQ; t++) {
        float a0 = p0, a1 = p1, a2 = p2, a3 = p3;
        if (j < H && t + 1 < TSEQ) {
            const float* xn = xgb + (size_t)(t + 1) * (4 * H);
            p0 = __ldg(xn + 0 * H + j);
            p1 = __ldg(xn + 1 * H + j);
            p2 = __ldg(xn + 2 * H + j);
            p3 = __ldg(xn + 3 * H + j);
        }
        if (j < H) {
#pragma unroll
            for (int k = 0; k < H; k++) {
                float hk = hs[wp][k];
                a0 = fmaf(hk, wr[0][k], a0);
                a1 = fmaf(hk, wr[1][k], a1);
                a2 = fmaf(hk, wr[2][k], a2);
                a3 = fmaf(hk, wr[3][k], a3);
            }
            float ig = sigmoidf_(a0);
            float fg = sigmoidf_(a1);
            float gg = tanhf_(a2);
            float og = sigmoidf_(a3);
            c = fg * c + ig * gg;
            h = og * tanhf_(c);
            if (WRITE_SEQ) hob[(size_t)t * H + j] = h;
        }
        __syncwarp();
        if (j < H) hs[wp][j] = h;
        __syncwarp();
    }
    if (!WRITE_SEQ && j < H) hob[j] = h;
}

// ---------------- launch ----------------
extern "C" void kernel_launch(void* const* d_in, const int* in_sizes, int n_in,
                              void* d_out, int out_size)
{
    const float* x      = (const float*)d_in[0];
    const float* conv_w = (const float*)d_in[1];
    const float* conv_b = (const float*)d_in[2];
    const float* Wih1   = (const float*)d_in[3];
    const float* Whh1   = (const float*)d_in[4];
    const float* bih1   = (const float*)d_in[5];
    const float* bhh1   = (const float*)d_in[6];
    const float* Wih2   = (const float*)d_in[7];
    const float* Whh2   = (const float*)d_in[8];
    const float* bih2   = (const float*)d_in[9];
    const float* bhh2   = (const float*)d_in[10];
    const float* Wih3   = (const float*)d_in[11];
    const float* Whh3   = (const float*)d_in[12];
    const float* bih3   = (const float*)d_in[13];
    const float* bhh3   = (const float*)d_in[14];
    float* out = (float*)d_out;

    float *conv_p, *xg1_p, *h1_p, *xg2_p, *h2_p, *xg3_p;
    cudaGetSymbolAddress((void**)&conv_p, g_conv);
    cudaGetSymbolAddress((void**)&xg1_p,  g_xg1);
    cudaGetSymbolAddress((void**)&h1_p,   g_h1);
    cudaGetSymbolAddress((void**)&xg2_p,  g_xg2);
    cudaGetSymbolAddress((void**)&h2_p,   g_h2);
    cudaGetSymbolAddress((void**)&xg3_p,  g_xg3);

    cudaFuncSetAttribute(conv_mma_kernel, cudaFuncAttributeMaxDynamicSharedMemorySize, CV_SMEM_BYTES);
    cudaFuncSetAttribute(xg1_mma_kernel,  cudaFuncAttributeMaxDynamicSharedMemorySize, XG_SMEM_BYTES);

    // 1) conv (tf32 tensor core)
    conv_mma_kernel<<<dim3(8, BATCH), 256, CV_SMEM_BYTES>>>(x, conv_w, conv_b);

    // 2) xg1 (tf32 tensor core)
    xg1_mma_kernel<<<MROWS / 128, 256, XG_SMEM_BYTES>>>(conv_p, Wih1, bih1, bhh1, xg1_p);

    // 3) LSTM1
    lstm_kernel<H1, true><<<BATCH / 4, 128>>>(xg1_p, Whh1, h1_p);

    // 4) xg2 (scalar)
    gemm_bias_kernel<32><<<dim3(MROWS / 64, 1), 256>>>(h1_p, Wih2, bih2, bhh2, xg2_p, 4 * H2);

    // 5) LSTM2
    lstm_kernel<H2, true><<<BATCH / 4, 128>>>(xg2_p, Whh2, h2_p);

    // 6) xg3 (scalar)
    gemm_bias_kernel<16><<<dim3(MROWS / 64, 2), 256>>>(h2_p, Wih3, bih3, bhh3, xg3_p, 4 * H3);

    // 7) LSTM3 -> final h only
    lstm_kernel<H3, false><<<BATCH / 4, 128>>>(xg3_p, Whh3, out);

    (void)in_sizes; (void)n_in; (void)out_size;
}

// round 3
// speedup vs baseline: 2.8444x; 1.1733x over previous
#include <cuda_runtime.h>
#include <cuda_bf16.h>
#include <cstdint>

// Problem constants
#define BATCH   512
#define CIN     128
#define LIN     1024
#define KW      5
#define LOUT    1020
#define TSEQ    1020
#define H1      32
#define H2      16
#define H3      32
#define MROWS   (BATCH * TSEQ)   // 522240

// ---------------- scratch ----------------
__device__ float g_conv[(size_t)BATCH * CIN * LOUT];     // conv out == seq matrix [M,128]
__device__ float g_xg1 [(size_t)MROWS * 4 * H1];         // layer-1 input gates [M,128]

// ---------------- helpers ----------------
__device__ __forceinline__ float sigmoidf_(float x) {
    x = fminf(30.f, fmaxf(-30.f, x));
    return __fdividef(1.f, 1.f + __expf(-x));
}
__device__ __forceinline__ float tanhf_(float x) {
    x = fminf(15.f, fmaxf(-15.f, x));
    float e = __expf(2.f * x);
    return __fdividef(e - 1.f, e + 1.f);
}
__device__ __forceinline__ uint32_t f2tf32(float f) {
    uint32_t r;
    asm("cvt.rna.tf32.f32 %0, %1;" : "=r"(r) : "f"(f));
    return r;
}
__device__ __forceinline__ void mma_tf32(float c[4], const uint32_t a[4], uint32_t b0, uint32_t b1) {
    asm volatile(
        "mma.sync.aligned.m16n8k8.row.col.f32.tf32.tf32.f32 "
        "{%0,%1,%2,%3}, {%4,%5,%6,%7}, {%8,%9}, {%0,%1,%2,%3};"
        : "+f"(c[0]), "+f"(c[1]), "+f"(c[2]), "+f"(c[3])
        : "r"(a[0]), "r"(a[1]), "r"(a[2]), "r"(a[3]), "r"(b0), "r"(b1));
}
// packed dual-FMA (Blackwell f32x2)
__device__ __forceinline__ float2 ffma2(float2 a, float2 b, float2 c) {
    unsigned long long ua, ub, uc, ur;
    ua = *reinterpret_cast<unsigned long long*>(&a);
    ub = *reinterpret_cast<unsigned long long*>(&b);
    uc = *reinterpret_cast<unsigned long long*>(&c);
    asm("fma.rn.f32x2 %0, %1, %2, %3;" : "=l"(ur) : "l"(ua), "l"(ub), "l"(uc));
    return *reinterpret_cast<float2*>(&ur);
}

// =====================================================================
// conv1d via tf32 MMA (unchanged from round 2)
// =====================================================================
#define CV_WS_STRIDE 20
#define CV_XS_STRIDE 136
#define CV_WS_ELEMS  (5 * 128 * CV_WS_STRIDE)
#define CV_XS_ELEMS  (16 * CV_XS_STRIDE)
#define CV_SMEM_BYTES ((CV_WS_ELEMS + CV_XS_ELEMS) * 4)

__global__ __launch_bounds__(256) void conv_mma_kernel(
    const float* __restrict__ x, const float* __restrict__ w, const float* __restrict__ bias)
{
    extern __shared__ uint32_t smem_u[];
    uint32_t* Ws = smem_u;
    uint32_t* Xs = smem_u + CV_WS_ELEMS;

    const int b   = blockIdx.y;
    const int lb  = blockIdx.x * 128;
    const int tid = threadIdx.x;
    const int warp = tid >> 5;
    const int lane = tid & 31;
    const int g   = lane >> 2;
    const int t4  = lane & 3;
    const int warp_m = warp >> 1;
    const int warp_n = warp & 1;

    float acc[2][8][4];
#pragma unroll
    for (int mi = 0; mi < 2; mi++)
#pragma unroll
        for (int ni = 0; ni < 8; ni++)
#pragma unroll
            for (int e = 0; e < 4; e++) acc[mi][ni][e] = 0.f;

    const float* xb = x + (size_t)b * (CIN * LIN);

    for (int ci0 = 0; ci0 < CIN; ci0 += 16) {
        __syncthreads();
        for (int v = tid; v < 2560; v += 256) {
            int co = v / 20;
            int r4 = v - co * 20;
            const float4 wv = *reinterpret_cast<const float4*>(w + (size_t)co * 640 + ci0 * 5 + r4 * 4);
            float we[4] = {wv.x, wv.y, wv.z, wv.w};
#pragma unroll
            for (int e = 0; e < 4; e++) {
                int r = r4 * 4 + e;
                int cil = r / 5;
                int tap = r - cil * 5;
                Ws[((tap * 128) + co) * CV_WS_STRIDE + cil] = f2tf32(we[e]);
            }
        }
        for (int v = tid; v < 16 * 33; v += 256) {
            int row = v / 33;
            int p4  = v - row * 33;
            const float* xr = xb + (size_t)(ci0 + row) * LIN;
            int gl = lb + p4 * 4;
            uint32_t o[4];
            if (gl + 3 < LIN) {
                float4 xv = *reinterpret_cast<const float4*>(xr + gl);
                o[0] = f2tf32(xv.x); o[1] = f2tf32(xv.y); o[2] = f2tf32(xv.z); o[3] = f2tf32(xv.w);
            } else {
#pragma unroll
                for (int e = 0; e < 4; e++)
                    o[e] = (gl + e < LIN) ? f2tf32(xr[gl + e]) : 0u;
            }
            *reinterpret_cast<uint4*>(&Xs[row * CV_XS_STRIDE + p4 * 4]) = make_uint4(o[0], o[1], o[2], o[3]);
        }
        __syncthreads();

#pragma unroll
        for (int tap = 0; tap < 5; tap++) {
#pragma unroll
            for (int ks = 0; ks < 2; ks++) {
                const int k0 = ks * 8;
                uint32_t a[2][4];
#pragma unroll
                for (int mi = 0; mi < 2; mi++) {
                    int row = warp_m * 32 + mi * 16;
                    const uint32_t* wsb = Ws + tap * 128 * CV_WS_STRIDE;
                    a[mi][0] = wsb[(row + g)     * CV_WS_STRIDE + k0 + t4];
                    a[mi][1] = wsb[(row + 8 + g) * CV_WS_STRIDE + k0 + t4];
                    a[mi][2] = wsb[(row + g)     * CV_WS_STRIDE + k0 + t4 + 4];
                    a[mi][3] = wsb[(row + 8 + g) * CV_WS_STRIDE + k0 + t4 + 4];
                }
#pragma unroll
                for (int ni = 0; ni < 8; ni++) {
                    int col = warp_n * 64 + ni * 8 + g + tap;
                    uint32_t b0 = Xs[(k0 + t4)     * CV_XS_STRIDE + col];
                    uint32_t b1 = Xs[(k0 + t4 + 4) * CV_XS_STRIDE + col];
                    mma_tf32(acc[0][ni], a[0], b0, b1);
                    mma_tf32(acc[1][ni], a[1], b0, b1);
                }
            }
        }
    }

    float* ob = g_conv + (size_t)b * (CIN * LOUT);
#pragma unroll
    for (int mi = 0; mi < 2; mi++) {
        int row0 = warp_m * 32 + mi * 16 + g;
        float bv0 = bias[row0];
        float bv1 = bias[row0 + 8];
#pragma unroll
        for (int ni = 0; ni < 8; ni++) {
            int l = lb + warp_n * 64 + ni * 8 + 2 * t4;
            if (l + 1 < LOUT) {
                float2 v0 = make_float2(acc[mi][ni][0] + bv0, acc[mi][ni][1] + bv0);
                float2 v1 = make_float2(acc[mi][ni][2] + bv1, acc[mi][ni][3] + bv1);
                *reinterpret_cast<float2*>(ob + (size_t)row0 * LOUT + l) = v0;
                *reinterpret_cast<float2*>(ob + (size_t)(row0 + 8) * LOUT + l) = v1;
            } else if (l < LOUT) {
                ob[(size_t)row0 * LOUT + l]       = acc[mi][ni][0] + bv0;
                ob[(size_t)(row0 + 8) * LOUT + l] = acc[mi][ni][2] + bv1;
            }
        }
    }
}

// =====================================================================
// xg1 GEMM via tf32 MMA (unchanged from round 2)
// =====================================================================
#define XG_STRIDE 132
#define XG_SMEM_BYTES (2 * 128 * XG_STRIDE * 4)

__global__ __launch_bounds__(256) void xg1_mma_kernel(
    const float* __restrict__ A, const float* __restrict__ W,
    const float* __restrict__ b1, const float* __restrict__ b2,
    float* __restrict__ C)
{
    extern __shared__ uint32_t smem_u[];
    uint32_t* As = smem_u;
    uint32_t* Bs = smem_u + 128 * XG_STRIDE;

    const int row0 = blockIdx.x * 128;
    const int tid  = threadIdx.x;
    const int warp = tid >> 5;
    const int lane = tid & 31;
    const int g    = lane >> 2;
    const int t4   = lane & 3;
    const int warp_m = warp >> 1;
    const int warp_n = warp & 1;

    for (int v = tid; v < 128 * 32; v += 256) {
        int r  = v >> 5;
        int k4 = (v & 31) * 4;
        float4 av = *reinterpret_cast<const float4*>(A + (size_t)(row0 + r) * 128 + k4);
        *reinterpret_cast<uint4*>(&As[r * XG_STRIDE + k4]) =
            make_uint4(f2tf32(av.x), f2tf32(av.y), f2tf32(av.z), f2tf32(av.w));
        float4 wv = *reinterpret_cast<const float4*>(W + (size_t)r * 128 + k4);
        *reinterpret_cast<uint4*>(&Bs[r * XG_STRIDE + k4]) =
            make_uint4(f2tf32(wv.x), f2tf32(wv.y), f2tf32(wv.z), f2tf32(wv.w));
    }
    __syncthreads();

    float acc[2][8][4];
#pragma unroll
    for (int mi = 0; mi < 2; mi++)
#pragma unroll
        for (int ni = 0; ni < 8; ni++)
#pragma unroll
            for (int e = 0; e < 4; e++) acc[mi][ni][e] = 0.f;

#pragma unroll
    for (int k0 = 0; k0 < 128; k0 += 8) {
        uint32_t a[2][4];
#pragma unroll
        for (int mi = 0; mi < 2; mi++) {
            int row = warp_m * 32 + mi * 16;
            a[mi][0] = As[(row + g)     * XG_STRIDE + k0 + t4];
            a[mi][1] = As[(row + 8 + g) * XG_STRIDE + k0 + t4];
            a[mi][2] = As[(row + g)     * XG_STRIDE + k0 + t4 + 4];
            a[mi][3] = As[(row + 8 + g) * XG_STRIDE + k0 + t4 + 4];
        }
#pragma unroll
        for (int ni = 0; ni < 8; ni++) {
            int n = warp_n * 64 + ni * 8 + g;
            uint32_t b0 = Bs[n * XG_STRIDE + k0 + t4];
            uint32_t b1 = Bs[n * XG_STRIDE + k0 + t4 + 4];
            mma_tf32(acc[0][ni], a[0], b0, b1);
            mma_tf32(acc[1][ni], a[1], b0, b1);
        }
    }

#pragma unroll
    for (int mi = 0; mi < 2; mi++) {
        int r0 = row0 + warp_m * 32 + mi * 16 + g;
#pragma unroll
        for (int ni = 0; ni < 8; ni++) {
            int n = warp_n * 64 + ni * 8 + 2 * t4;
            float bb0 = b1[n] + b2[n];
            float bb1 = b1[n + 1] + b2[n + 1];
            *reinterpret_cast<float2*>(C + (size_t)r0 * 128 + n) =
                make_float2(acc[mi][ni][0] + bb0, acc[mi][ni][1] + bb1);
            *reinterpret_cast<float2*>(C + (size_t)(r0 + 8) * 128 + n) =
                make_float2(acc[mi][ni][2] + bb0, acc[mi][ni][3] + bb1);
        }
    }
}

// =====================================================================
// Fused LSTM1+LSTM2+LSTM3 (incl. xg2/xg3 matvecs), software-pipelined.
// 1 CTA = 1 batch, 128 threads = 4 role-warps:
//   role0: L1 recurrence (h1[t] at wall t), reads xg1 stream
//   role1: L2 gates (Wih2@h1 + Whh2@h2) -> h2[t] at wall t+1
//   role2: pre3[t] = Wih3@h2[t] + biases  at wall t+2
//   role3: L3 recurrence -> h3[t] at wall t+3; final h3 -> out
// All exchanges via double-buffered smem rings; 1 __syncthreads per wall.
// =====================================================================
__global__ __launch_bounds__(128) void fused_lstm_kernel(
    const float* __restrict__ xg1,
    const float* __restrict__ Whh1,
    const float* __restrict__ Wih2, const float* __restrict__ Whh2,
    const float* __restrict__ bih2, const float* __restrict__ bhh2,
    const float* __restrict__ Wih3, const float* __restrict__ Whh3,
    const float* __restrict__ bih3, const float* __restrict__ bhh3,
    float* __restrict__ out)
{
    __shared__ __align__(8) float h1s [2][32];
    __shared__ __align__(8) float h2s [2][16];
    __shared__ __align__(8) float pre3s[2][128];
    __shared__ __align__(8) float h3s [2][32];

    const int tid  = threadIdx.x;
    const int wid  = tid >> 5;
    const int lane = tid & 31;
    const int b    = blockIdx.x;
    const int role = (wid + b) & 3;   // rotate roles across CTAs to balance SMSPs

    // zero rings
    for (int i = tid; i < 64; i += 128)  { h1s[0][i & 31] = 0.f; }
    if (tid < 32) { h2s[0][tid & 15] = 0.f; h2s[1][tid & 15] = 0.f; }
    for (int i = tid; i < 256; i += 128) { pre3s[i >> 7][i & 127] = 0.f; }
    if (tid < 64) { h3s[tid >> 5][tid & 31] = 0.f; }
    // (h1s[1] covered by first loop: i in [0,64) -> slots 0 and 1)

    // ---- per-role register state ----
    float2 wr0[4][16];            // role0: Whh1 rows g*32+lane
    float2 w2ia[16], w2ib[16];    // role1: Wih2 rows pa, pb
    float2 w2ha[8],  w2hb[8];     // role1: Whh2 rows pa, pb
    float  bias2a = 0.f, bias2b = 0.f;
    float2 w3i[4][8];             // role2: Wih3 rows lane+32g
    float  bias3[4];
    float2 w3h[4][16];            // role3: Whh3 rows g*32+lane

    float p0 = 0.f, p1 = 0.f, p2 = 0.f, p3 = 0.f;  // role0 xg1 prefetch
    float cst = 0.f;                                // cell state (role0: c1[lane], role1: c2[lane<16], role3: c3[lane])
    float h3loc = 0.f;

    const float* xb = xg1 + (size_t)b * TSEQ * 128 + lane;

    if (role == 0) {
#pragma unroll
        for (int g = 0; g < 4; g++)
#pragma unroll
            for (int k = 0; k < 16; k++)
                wr0[g][k] = *reinterpret_cast<const float2*>(Whh1 + (size_t)(g * 32 + lane) * 32 + 2 * k);
        p0 = xb[0]; p1 = xb[32]; p2 = xb[64]; p3 = xb[96];
    } else if (role == 1) {
        int j = lane & 15, hi = lane >> 4;
        int pa = hi * 16 + j;         // i (hi=0) / f (hi=1) gate rows
        int pb = 32 + hi * 16 + j;    // g (hi=0) / o (hi=1) gate rows
#pragma unroll
        for (int k = 0; k < 16; k++) {
            w2ia[k] = *reinterpret_cast<const float2*>(Wih2 + (size_t)pa * 32 + 2 * k);
            w2ib[k] = *reinterpret_cast<const float2*>(Wih2 + (size_t)pb * 32 + 2 * k);
        }
#pragma unroll
        for (int k = 0; k < 8; k++) {
            w2ha[k] = *reinterpret_cast<const float2*>(Whh2 + (size_t)pa * 16 + 2 * k);
            w2hb[k] = *reinterpret_cast<const float2*>(Whh2 + (size_t)pb * 16 + 2 * k);
        }
        bias2a = bih2[pa] + bhh2[pa];
        bias2b = bih2[pb] + bhh2[pb];
    } else if (role == 2) {
#pragma unroll
        for (int g = 0; g < 4; g++) {
            int p = lane + 32 * g;
#pragma unroll
            for (int k = 0; k < 8; k++)
                w3i[g][k] = *reinterpret_cast<const float2*>(Wih3 + (size_t)p * 16 + 2 * k);
            bias3[g] = bih3[p] + bhh3[p];
        }
    } else {
#pragma unroll
        for (int g = 0; g < 4; g++)
#pragma unroll
            for (int k = 0; k < 16; k++)
                w3h[g][k] = *reinterpret_cast<const float2*>(Whh3 + (size_t)(g * 32 + lane) * 32 + 2 * k);
    }
    __syncthreads();

    for (int s = 0; s < TSEQ + 3; s++) {
        const int rs = (s - 1) & 1;
        const int ws = s & 1;

        if (role == 0) {
            if (s < TSEQ) {
                float2 a0 = make_float2(p0, 0.f), a1 = make_float2(p1, 0.f);
                float2 a2 = make_float2(p2, 0.f), a3 = make_float2(p3, 0.f);
                if (s + 1 < TSEQ) {
                    const float* xn = xb + (size_t)(s + 1) * 128;
                    p0 = __ldg(xn); p1 = __ldg(xn + 32); p2 = __ldg(xn + 64); p3 = __ldg(xn + 96);
                }
                const float2* hp = reinterpret_cast<const float2*>(h1s[rs]);
#pragma unroll
                for (int k = 0; k < 16; k++) {
                    float2 hv = hp[k];
                    a0 = ffma2(hv, wr0[0][k], a0);
                    a1 = ffma2(hv, wr0[1][k], a1);
                    a2 = ffma2(hv, wr0[2][k], a2);
                    a3 = ffma2(hv, wr0[3][k], a3);
                }
                float ig = sigmoidf_(a0.x + a0.y);
                float fg = sigmoidf_(a1.x + a1.y);
                float gg = tanhf_(a2.x + a2.y);
                float og = sigmoidf_(a3.x + a3.y);
                cst = fg * cst + ig * gg;
                h1s[ws][lane] = og * tanhf_(cst);
            }
        } else if (role == 1) {
            if (s >= 1 && s <= TSEQ) {
                float2 aa = make_float2(bias2a, 0.f);
                float2 ab = make_float2(bias2b, 0.f);
                const float2* h1p = reinterpret_cast<const float2*>(h1s[rs]);
#pragma unroll
                for (int k = 0; k < 16; k++) {
                    float2 hv = h1p[k];
                    aa = ffma2(hv, w2ia[k], aa);
                    ab = ffma2(hv, w2ib[k], ab);
                }
                const float2* h2p = reinterpret_cast<const float2*>(h2s[rs]);
#pragma unroll
                for (int k = 0; k < 8; k++) {
                    float2 hv = h2p[k];
                    aa = ffma2(hv, w2ha[k], aa);
                    ab = ffma2(hv, w2hb[k], ab);
                }
                float va = aa.x + aa.y;
                float vb = ab.x + ab.y;
                // lane j<16 holds i (va) and g (vb); lane j+16 holds f (va) and o (vb)
                float fpre = __shfl_sync(0xffffffffu, va, (lane & 15) + 16);
                float opre = __shfl_sync(0xffffffffu, vb, (lane & 15) + 16);
                if (lane < 16) {
                    float ig = sigmoidf_(va);
                    float gg = tanhf_(vb);
                    float fg = sigmoidf_(fpre);
                    float og = sigmoidf_(opre);
                    cst = fg * cst + ig * gg;
                    h2s[ws][lane] = og * tanhf_(cst);
                }
            }
        } else if (role == 2) {
            if (s >= 2 && s <= TSEQ + 1) {
                float2 acc[4];
#pragma unroll
                for (int g = 0; g < 4; g++) acc[g] = make_float2(bias3[g], 0.f);
                const float2* h2p = reinterpret_cast<const float2*>(h2s[rs]);
#pragma unroll
                for (int k = 0; k < 8; k++) {
                    float2 hv = h2p[k];
#pragma unroll
                    for (int g = 0; g < 4; g++) acc[g] = ffma2(hv, w3i[g][k], acc[g]);
                }
#pragma unroll
                for (int g = 0; g < 4; g++)
                    pre3s[ws][lane + 32 * g] = acc[g].x + acc[g].y;
            }
        } else {
            if (s >= 3) {
                float2 a0 = make_float2(pre3s[rs][lane],      0.f);
                float2 a1 = make_float2(pre3s[rs][lane + 32], 0.f);
                float2 a2 = make_float2(pre3s[rs][lane + 64], 0.f);
                float2 a3 = make_float2(pre3s[rs][lane + 96], 0.f);
                const float2* h3p = reinterpret_cast<const float2*>(h3s[rs]);
#pragma unroll
                for (int k = 0; k < 16; k++) {
                    float2 hv = h3p[k];
                    a0 = ffma2(hv, w3h[0][k], a0);
                    a1 = ffma2(hv, w3h[1][k], a1);
                    a2 = ffma2(hv, w3h[2][k], a2);
                    a3 = ffma2(hv, w3h[3][k], a3);
                }
                float ig = sigmoidf_(a0.x + a0.y);
                float fg = sigmoidf_(a1.x + a1.y);
                float gg = tanhf_(a2.x + a2.y);
                float og = sigmoidf_(a3.x + a3.y);
                cst = fg * cst + ig * gg;
                h3loc = og * tanhf_(cst);
                h3s[ws][lane] = h3loc;
            }
        }
        __syncthreads();
    }

    if (role == 3) out[(size_t)b * 32 + lane] = h3loc;
}

// ---------------- launch ----------------
extern "C" void kernel_launch(void* const* d_in, const int* in_sizes, int n_in,
                              void* d_out, int out_size)
{
    const float* x      = (const float*)d_in[0];
    const float* conv_w = (const float*)d_in[1];
    const float* conv_b = (const float*)d_in[2];
    const float* Wih1   = (const float*)d_in[3];
    const float* Whh1   = (const float*)d_in[4];
    const float* bih1   = (const float*)d_in[5];
    const float* bhh1   = (const float*)d_in[6];
    const float* Wih2   = (const float*)d_in[7];
    const float* Whh2   = (const float*)d_in[8];
    const float* bih2   = (const float*)d_in[9];
    const float* bhh2   = (const float*)d_in[10];
    const float* Wih3   = (const float*)d_in[11];
    const float* Whh3   = (const float*)d_in[12];
    const float* bih3   = (const float*)d_in[13];
    const float* bhh3   = (const float*)d_in[14];
    float* out = (float*)d_out;

    float *conv_p, *xg1_p;
    cudaGetSymbolAddress((void**)&conv_p, g_conv);
    cudaGetSymbolAddress((void**)&xg1_p,  g_xg1);

    cudaFuncSetAttribute(conv_mma_kernel, cudaFuncAttributeMaxDynamicSharedMemorySize, CV_SMEM_BYTES);
    cudaFuncSetAttribute(xg1_mma_kernel,  cudaFuncAttributeMaxDynamicSharedMemorySize, XG_SMEM_BYTES);

    // 1) conv (tf32 tensor core) -> g_conv
    conv_mma_kernel<<<dim3(8, BATCH), 256, CV_SMEM_BYTES>>>(x, conv_w, conv_b);

    // 2) xg1 = seq @ Wih1^T + biases (tf32 tensor core)
    xg1_mma_kernel<<<MROWS / 128, 256, XG_SMEM_BYTES>>>(conv_p, Wih1, bih1, bhh1, xg1_p);

    // 3) fused LSTM1+2+3 -> d_out
    fused_lstm_kernel<<<BATCH, 128>>>(xg1_p, Whh1, Wih2, Whh2, bih2, bhh2,
                                      Wih3, Whh3, bih3, bhh3, out);

    (void)in_sizes; (void)n_in; (void)out_size;
}

// round 4
// speedup vs baseline: 3.0892x; 1.0861x over previous
#include <cuda_runtime.h>
#include <cuda_bf16.h>
#include <cstdint>

// Problem constants
#define BATCH   512
#define CIN     128
#define LIN     1024
#define KW      5
#define LOUT    1020
#define TSEQ    1020
#define H1      32
#define H2      16
#define H3      32
#define MROWS   (BATCH * TSEQ)   // 522240

// ---------------- scratch ----------------
__device__ float g_conv[(size_t)BATCH * CIN * LOUT];     // conv out == seq matrix [M,128]
__device__ float g_xg1 [(size_t)MROWS * 4 * H1];         // layer-1 input gates [M,128]
__device__ float g_wt  [5 * 128 * 128];                   // prepacked conv W: [tap][co][ci], tf32 bits

// ---------------- helpers ----------------
__device__ __forceinline__ float sigmoid_fast(float x) {
    // 1/(1+2^(-x*log2e)); inf-safe: rcp(inf)=0, rcp(1)=1
    float e = exp2f(x * -1.442695041f);
    float r; asm("rcp.approx.f32 %0, %1;" : "=f"(r) : "f"(1.f + e));
    return r;
}
__device__ __forceinline__ float tanh_fast(float x) {
    // 1 - 2/(2^(2x*log2e)+1); inf-safe
    float e = exp2f(x * 2.885390082f);
    float r; asm("rcp.approx.f32 %0, %1;" : "=f"(r) : "f"(1.f + e));
    return fmaf(-2.f, r, 1.f);
}
__device__ __forceinline__ uint32_t f2tf32(float f) {
    uint32_t r;
    asm("cvt.rna.tf32.f32 %0, %1;" : "=r"(r) : "f"(f));
    return r;
}
__device__ __forceinline__ void mma_tf32(float c[4], const uint32_t a[4], uint32_t b0, uint32_t b1) {
    asm volatile(
        "mma.sync.aligned.m16n8k8.row.col.f32.tf32.tf32.f32 "
        "{%0,%1,%2,%3}, {%4,%5,%6,%7}, {%8,%9}, {%0,%1,%2,%3};"
        : "+f"(c[0]), "+f"(c[1]), "+f"(c[2]), "+f"(c[3])
        : "r"(a[0]), "r"(a[1]), "r"(a[2]), "r"(a[3]), "r"(b0), "r"(b1));
}
__device__ __forceinline__ float2 ffma2(float2 a, float2 b, float2 c) {
    unsigned long long ua, ub, uc, ur;
    ua = *reinterpret_cast<unsigned long long*>(&a);
    ub = *reinterpret_cast<unsigned long long*>(&b);
    uc = *reinterpret_cast<unsigned long long*>(&c);
    asm("fma.rn.f32x2 %0, %1, %2, %3;" : "=l"(ur) : "l"(ua), "l"(ub), "l"(uc));
    return *reinterpret_cast<float2*>(&ur);
}
__device__ __forceinline__ uint32_t smem_u32(const void* p) {
    uint32_t a;
    asm("{ .reg .u64 t; cvta.to.shared.u64 t, %1; cvt.u32.u64 %0, t; }" : "=r"(a) : "l"(p));
    return a;
}
__device__ __forceinline__ void cp16(uint32_t dst, const void* src) {
    asm volatile("cp.async.ca.shared.global [%0], [%1], 16;" :: "r"(dst), "l"(src));
}
__device__ __forceinline__ void cp16n(uint32_t dst, const void* src, int nbytes) {
    asm volatile("cp.async.ca.shared.global [%0], [%1], 16, %2;" :: "r"(dst), "l"(src), "r"(nbytes));
}

// =====================================================================
// W prepack: g_wt[tap][co][ci] = tf32(w[co][ci][tap])
// =====================================================================
__global__ void prep_w_kernel(const float* __restrict__ w) {
    int i = blockIdx.x * 256 + threadIdx.x;
    if (i < 5 * 128 * 128) {
        int ci = i & 127;
        int r  = i >> 7;
        int co  = r & 127;
        int tap = r >> 7;
        g_wt[i] = __uint_as_float(f2tf32(w[((size_t)co * 128 + ci) * 5 + tap]));
    }
}

// =====================================================================
// conv1d via tf32 MMA, 128co x 256l tile, cp.async double-buffered.
// grid (4, 512), block 256 (8 warps: warp_m in [0,4), warp_n in [0,2)).
// smem: Ws[2][5*128*20] + Xs[2][16*264]  (f32/tf32 bit patterns)
// =====================================================================
#define CV2_WS_ST   12800          // floats per W stage (5*128*20)
#define CV2_XS_ST   (16 * 264)     // floats per X stage
#define CV2_XS_BASE (2 * CV2_WS_ST)
#define CV2_SMEM_BYTES ((2 * CV2_WS_ST + 2 * CV2_XS_ST) * 4)   // 136192

__global__ __launch_bounds__(256, 1) void conv2_kernel(
    const float* __restrict__ x, const float* __restrict__ bias)
{
    extern __shared__ float smf[];
    const uint32_t sbase = smem_u32(smf);
    const uint32_t* Su = reinterpret_cast<const uint32_t*>(smf);

    const int b   = blockIdx.y;
    const int lb  = blockIdx.x * 256;
    const int tid = threadIdx.x;
    const int warp = tid >> 5;
    const int lane = tid & 31;
    const int g   = lane >> 2;
    const int t4  = lane & 3;
    const int warp_m = warp >> 1;   // 32 co per warp
    const int warp_n = warp & 1;    // 128 l per warp

    const float* xb = x + (size_t)b * (CIN * LIN);

    float acc[2][16][4];
#pragma unroll
    for (int mi = 0; mi < 2; mi++)
#pragma unroll
        for (int ni = 0; ni < 16; ni++)
#pragma unroll
            for (int e = 0; e < 4; e++) acc[mi][ni][e] = 0.f;

    // ---- async issue helpers (inlined) ----
    auto issue_chunk = [&](int c, int s) {
        // W: 640 rows x 16 floats (64B) -> stride-20 smem rows
#pragma unroll
        for (int i = 0; i < 10; i++) {
            int v = tid + i * 256;           // 0..2559
            int row = v >> 2, q = v & 3;
            uint32_t d = sbase + (uint32_t)(s * CV2_WS_ST + row * 20 + q * 4) * 4;
            cp16(d, g_wt + (size_t)row * 128 + c * 16 + q * 4);
        }
        // X: 16 rows x 260 floats (65 x 16B), tail zero-filled
#pragma unroll
        for (int i = 0; i < 5; i++) {
            int v = tid + i * 256;
            if (v < 1040) {
                int row = v / 65, q = v - row * 65;
                int gl = lb + q * 4;
                int nb = (LIN - gl) * 4;
                nb = nb < 0 ? 0 : (nb > 16 ? 16 : nb);
                const float* sp = (nb > 0) ? (xb + (size_t)(c * 16 + row) * LIN + gl) : xb;
                uint32_t d = sbase + (uint32_t)(CV2_XS_BASE + s * CV2_XS_ST + row * 264 + q * 4) * 4;
                cp16n(d, sp, nb);
            }
        }
    };

    for (int c = 0; c < 8; c++) {
        const int s = c & 1;
        if (c == 0) {
            issue_chunk(0, 0);
            asm volatile("cp.async.commit_group;");
        }
        if (c + 1 < 8) {
            issue_chunk(c + 1, s ^ 1);
            asm volatile("cp.async.commit_group;");
            asm volatile("cp.async.wait_group 1;");
        } else {
            asm volatile("cp.async.wait_group 0;");
        }
        __syncthreads();

        const uint32_t* Wst = Su + s * CV2_WS_ST;
        const uint32_t* Xst = Su + CV2_XS_BASE + s * CV2_XS_ST;
#pragma unroll
        for (int tap = 0; tap < 5; tap++) {
#pragma unroll
            for (int ks = 0; ks < 2; ks++) {
                const int k0 = ks * 8;
                uint32_t a[2][4];
#pragma unroll
                for (int mi = 0; mi < 2; mi++) {
                    int row = tap * 128 + warp_m * 32 + mi * 16;
                    a[mi][0] = Wst[(row + g)     * 20 + k0 + t4];
                    a[mi][1] = Wst[(row + 8 + g) * 20 + k0 + t4];
                    a[mi][2] = Wst[(row + g)     * 20 + k0 + t4 + 4];
                    a[mi][3] = Wst[(row + 8 + g) * 20 + k0 + t4 + 4];
                }
#pragma unroll
                for (int ni = 0; ni < 16; ni++) {
                    int col = warp_n * 128 + ni * 8 + g + tap;
                    uint32_t b0 = Xst[(k0 + t4)     * 264 + col];
                    uint32_t b1 = Xst[(k0 + t4 + 4) * 264 + col];
                    mma_tf32(acc[0][ni], a[0], b0, b1);
                    mma_tf32(acc[1][ni], a[1], b0, b1);
                }
            }
        }
        __syncthreads();
    }

    // ---- epilogue: +bias, store [co][l]
    float* ob = g_conv + (size_t)b * (CIN * LOUT);
#pragma unroll
    for (int mi = 0; mi < 2; mi++) {
        int row0 = warp_m * 32 + mi * 16 + g;
        float bv0 = bias[row0];
        float bv1 = bias[row0 + 8];
#pragma unroll
        for (int ni = 0; ni < 16; ni++) {
            int l = lb + warp_n * 128 + ni * 8 + 2 * t4;
            if (l + 1 < LOUT) {
                *reinterpret_cast<float2*>(ob + (size_t)row0 * LOUT + l) =
                    make_float2(acc[mi][ni][0] + bv0, acc[mi][ni][1] + bv0);
                *reinterpret_cast<float2*>(ob + (size_t)(row0 + 8) * LOUT + l) =
                    make_float2(acc[mi][ni][2] + bv1, acc[mi][ni][3] + bv1);
            } else if (l < LOUT) {
                ob[(size_t)row0 * LOUT + l]       = acc[mi][ni][0] + bv0;
                ob[(size_t)(row0 + 8) * LOUT + l] = acc[mi][ni][2] + bv1;
            }
        }
    }
}

// =====================================================================
// xg1 GEMM via tf32 MMA (unchanged)
// =====================================================================
#define XG_STRIDE 132
#define XG_SMEM_BYTES (2 * 128 * XG_STRIDE * 4)

__global__ __launch_bounds__(256) void xg1_mma_kernel(
    const float* __restrict__ A, const float* __restrict__ W,
    const float* __restrict__ b1, const float* __restrict__ b2,
    float* __restrict__ C)
{
    extern __shared__ uint32_t smem_u[];
    uint32_t* As = smem_u;
    uint32_t* Bs = smem_u + 128 * XG_STRIDE;

    const int row0 = blockIdx.x * 128;
    const int tid  = threadIdx.x;
    const int warp = tid >> 5;
    const int lane = tid & 31;
    const int g    = lane >> 2;
    const int t4   = lane & 3;
    const int warp_m = warp >> 1;
    const int warp_n = warp & 1;

    for (int v = tid; v < 128 * 32; v += 256) {
        int r  = v >> 5;
        int k4 = (v & 31) * 4;
        float4 av = *reinterpret_cast<const float4*>(A + (size_t)(row0 + r) * 128 + k4);
        *reinterpret_cast<uint4*>(&As[r * XG_STRIDE + k4]) =
            make_uint4(f2tf32(av.x), f2tf32(av.y), f2tf32(av.z), f2tf32(av.w));
        float4 wv = *reinterpret_cast<const float4*>(W + (size_t)r * 128 + k4);
        *reinterpret_cast<uint4*>(&Bs[r * XG_STRIDE + k4]) =
            make_uint4(f2tf32(wv.x), f2tf32(wv.y), f2tf32(wv.z), f2tf32(wv.w));
    }
    __syncthreads();

    float acc[2][8][4];
#pragma unroll
    for (int mi = 0; mi < 2; mi++)
#pragma unroll
        for (int ni = 0; ni < 8; ni++)
#pragma unroll
            for (int e = 0; e < 4; e++) acc[mi][ni][e] = 0.f;

#pragma unroll
    for (int k0 = 0; k0 < 128; k0 += 8) {
        uint32_t a[2][4];
#pragma unroll
        for (int mi = 0; mi < 2; mi++) {
            int row = warp_m * 32 + mi * 16;
            a[mi][0] = As[(row + g)     * XG_STRIDE + k0 + t4];
            a[mi][1] = As[(row + 8 + g) * XG_STRIDE + k0 + t4];
            a[mi][2] = As[(row + g)     * XG_STRIDE + k0 + t4 + 4];
            a[mi][3] = As[(row + 8 + g) * XG_STRIDE + k0 + t4 + 4];
        }
#pragma unroll
        for (int ni = 0; ni < 8; ni++) {
            int n = warp_n * 64 + ni * 8 + g;
            uint32_t b0 = Bs[n * XG_STRIDE + k0 + t4];
            uint32_t b1 = Bs[n * XG_STRIDE + k0 + t4 + 4];
            mma_tf32(acc[0][ni], a[0], b0, b1);
            mma_tf32(acc[1][ni], a[1], b0, b1);
        }
    }

#pragma unroll
    for (int mi = 0; mi < 2; mi++) {
        int r0 = row0 + warp_m * 32 + mi * 16 + g;
#pragma unroll
        for (int ni = 0; ni < 8; ni++) {
            int n = warp_n * 64 + ni * 8 + 2 * t4;
            float bb0 = b1[n] + b2[n];
            float bb1 = b1[n + 1] + b2[n + 1];
            *reinterpret_cast<float2*>(C + (size_t)r0 * 128 + n) =
                make_float2(acc[mi][ni][0] + bb0, acc[mi][ni][1] + bb1);
            *reinterpret_cast<float2*>(C + (size_t)(r0 + 8) * 128 + n) =
                make_float2(acc[mi][ni][2] + bb0, acc[mi][ni][3] + bb1);
        }
    }
}

// =====================================================================
// Fused LSTM1+2+3, role-pipelined, fast activations
// =====================================================================
__global__ __launch_bounds__(128) void fused_lstm_kernel(
    const float* __restrict__ xg1,
    const float* __restrict__ Whh1,
    const float* __restrict__ Wih2, const float* __restrict__ Whh2,
    const float* __restrict__ bih2, const float* __restrict__ bhh2,
    const float* __restrict__ Wih3, const float* __restrict__ Whh3,
    const float* __restrict__ bih3, const float* __restrict__ bhh3,
    float* __restrict__ out)
{
    __shared__ __align__(8) float h1s [2][32];
    __shared__ __align__(8) float h2s [2][16];
    __shared__ __align__(8) float pre3s[2][128];
    __shared__ __align__(8) float h3s [2][32];

    const int tid  = threadIdx.x;
    const int wid  = tid >> 5;
    const int lane = tid & 31;
    const int b    = blockIdx.x;
    const int role = (wid + b) & 3;

    for (int i = tid; i < 64; i += 128)  { h1s[0][i & 31] = 0.f; }
    if (tid < 32) { h2s[0][tid & 15] = 0.f; h2s[1][tid & 15] = 0.f; }
    for (int i = tid; i < 256; i += 128) { pre3s[i >> 7][i & 127] = 0.f; }
    if (tid < 64) { h3s[tid >> 5][tid & 31] = 0.f; }

    float2 wr0[4][16];
    float2 w2ia[16], w2ib[16];
    float2 w2ha[8],  w2hb[8];
    float  bias2a = 0.f, bias2b = 0.f;
    float2 w3i[4][8];
    float  bias3[4];
    float2 w3h[4][16];

    float p0 = 0.f, p1 = 0.f, p2 = 0.f, p3 = 0.f;
    float cst = 0.f;
    float h3loc = 0.f;

    const float* xb = xg1 + (size_t)b * TSEQ * 128 + lane;

    if (role == 0) {
#pragma unroll
        for (int g = 0; g < 4; g++)
#pragma unroll
            for (int k = 0; k < 16; k++)
                wr0[g][k] = *reinterpret_cast<const float2*>(Whh1 + (size_t)(g * 32 + lane) * 32 + 2 * k);
        p0 = xb[0]; p1 = xb[32]; p2 = xb[64]; p3 = xb[96];
    } else if (role == 1) {
        int j = lane & 15, hi = lane >> 4;
        int pa = hi * 16 + j;
        int pb = 32 + hi * 16 + j;
#pragma unroll
        for (int k = 0; k < 16; k++) {
            w2ia[k] = *reinterpret_cast<const float2*>(Wih2 + (size_t)pa * 32 + 2 * k);
            w2ib[k] = *reinterpret_cast<const float2*>(Wih2 + (size_t)pb * 32 + 2 * k);
        }
#pragma unroll
        for (int k = 0; k < 8; k++) {
            w2ha[k] = *reinterpret_cast<const float2*>(Whh2 + (size_t)pa * 16 + 2 * k);
            w2hb[k] = *reinterpret_cast<const float2*>(Whh2 + (size_t)pb * 16 + 2 * k);
        }
        bias2a = bih2[pa] + bhh2[pa];
        bias2b = bih2[pb] + bhh2[pb];
    } else if (role == 2) {
#pragma unroll
        for (int g = 0; g < 4; g++) {
            int p = lane + 32 * g;
#pragma unroll
            for (int k = 0; k < 8; k++)
                w3i[g][k] = *reinterpret_cast<const float2*>(Wih3 + (size_t)p * 16 + 2 * k);
            bias3[g] = bih3[p] + bhh3[p];
        }
    } else {
#pragma unroll
        for (int g = 0; g < 4; g++)
#pragma unroll
            for (int k = 0; k < 16; k++)
                w3h[g][k] = *reinterpret_cast<const float2*>(Whh3 + (size_t)(g * 32 + lane) * 32 + 2 * k);
    }
    __syncthreads();

    for (int s = 0; s < TSEQ + 3; s++) {
        const int rs = (s - 1) & 1;
        const int ws = s & 1;

        if (role == 0) {
            if (s < TSEQ) {
                float2 a0 = make_float2(p0, 0.f), a1 = make_float2(p1, 0.f);
                float2 a2 = make_float2(p2, 0.f), a3 = make_float2(p3, 0.f);
                if (s + 1 < TSEQ) {
                    const float* xn = xb + (size_t)(s + 1) * 128;
                    p0 = __ldg(xn); p1 = __ldg(xn + 32); p2 = __ldg(xn + 64); p3 = __ldg(xn + 96);
                }
                const float2* hp = reinterpret_cast<const float2*>(h1s[rs]);
#pragma unroll
                for (int k = 0; k < 16; k++) {
                    float2 hv = hp[k];
                    a0 = ffma2(hv, wr0[0][k], a0);
                    a1 = ffma2(hv, wr0[1][k], a1);
                    a2 = ffma2(hv, wr0[2][k], a2);
                    a3 = ffma2(hv, wr0[3][k], a3);
                }
                float ig = sigmoid_fast(a0.x + a0.y);
                float fg = sigmoid_fast(a1.x + a1.y);
                float gg = tanh_fast(a2.x + a2.y);
                float og = sigmoid_fast(a3.x + a3.y);
                cst = fg * cst + ig * gg;
                h1s[ws][lane] = og * tanh_fast(cst);
            }
        } else if (role == 1) {
            if (s >= 1 && s <= TSEQ) {
                float2 aa = make_float2(bias2a, 0.f);
                float2 ab = make_float2(bias2b, 0.f);
                const float2* h1p = reinterpret_cast<const float2*>(h1s[rs]);
#pragma unroll
                for (int k = 0; k < 16; k++) {
                    float2 hv = h1p[k];
                    aa = ffma2(hv, w2ia[k], aa);
                    ab = ffma2(hv, w2ib[k], ab);
                }
                const float2* h2p = reinterpret_cast<const float2*>(h2s[rs]);
#pragma unroll
                for (int k = 0; k < 8; k++) {
                    float2 hv = h2p[k];
                    aa = ffma2(hv, w2ha[k], aa);
                    ab = ffma2(hv, w2hb[k], ab);
                }
                float va = aa.x + aa.y;
                float vb = ab.x + ab.y;
                float fpre = __shfl_sync(0xffffffffu, va, (lane & 15) + 16);
                float opre = __shfl_sync(0xffffffffu, vb, (lane & 15) + 16);
                if (lane < 16) {
                    float ig = sigmoid_fast(va);
                    float gg = tanh_fast(vb);
                    float fg = sigmoid_fast(fpre);
                    float og = sigmoid_fast(opre);
                    cst = fg * cst + ig * gg;
                    h2s[ws][lane] = og * tanh_fast(cst);
                }
            }
        } else if (role == 2) {
            if (s >= 2 && s <= TSEQ + 1) {
                float2 acc2[4];
#pragma unroll
                for (int g = 0; g < 4; g++) acc2[g] = make_float2(bias3[g], 0.f);
                const float2* h2p = reinterpret_cast<const float2*>(h2s[rs]);
#pragma unroll
                for (int k = 0; k < 8; k++) {
                    float2 hv = h2p[k];
#pragma unroll
                    for (int g = 0; g < 4; g++) acc2[g] = ffma2(hv, w3i[g][k], acc2[g]);
                }
#pragma unroll
                for (int g = 0; g < 4; g++)
                    pre3s[ws][lane + 32 * g] = acc2[g].x + acc2[g].y;
            }
        } else {
            if (s >= 3) {
                float2 a0 = make_float2(pre3s[rs][lane],      0.f);
                float2 a1 = make_float2(pre3s[rs][lane + 32], 0.f);
                float2 a2 = make_float2(pre3s[rs][lane + 64], 0.f);
                float2 a3 = make_float2(pre3s[rs][lane + 96], 0.f);
                const float2* h3p = reinterpret_cast<const float2*>(h3s[rs]);
#pragma unroll
                for (int k = 0; k < 16; k++) {
                    float2 hv = h3p[k];
                    a0 = ffma2(hv, w3h[0][k], a0);
                    a1 = ffma2(hv, w3h[1][k], a1);
                    a2 = ffma2(hv, w3h[2][k], a2);
                    a3 = ffma2(hv, w3h[3][k], a3);
                }
                float ig = sigmoid_fast(a0.x + a0.y);
                float fg = sigmoid_fast(a1.x + a1.y);
                float gg = tanh_fast(a2.x + a2.y);
                float og = sigmoid_fast(a3.x + a3.y);
                cst = fg * cst + ig * gg;
                h3loc = og * tanh_fast(cst);
                h3s[ws][lane] = h3loc;
            }
        }
        __syncthreads();
    }

    if (role == 3) out[(size_t)b * 32 + lane] = h3loc;
}

// ---------------- launch ----------------
extern "C" void kernel_launch(void* const* d_in, const int* in_sizes, int n_in,
                              void* d_out, int out_size)
{
    const float* x      = (const float*)d_in[0];
    const float* conv_w = (const float*)d_in[1];
    const float* conv_b = (const float*)d_in[2];
    const float* Wih1   = (const float*)d_in[3];
    const float* Whh1   = (const float*)d_in[4];
    const float* bih1   = (const float*)d_in[5];
    const float* bhh1   = (const float*)d_in[6];
    const float* Wih2   = (const float*)d_in[7];
    const float* Whh2   = (const float*)d_in[8];
    const float* bih2   = (const float*)d_in[9];
    const float* bhh2   = (const float*)d_in[10];
    const float* Wih3   = (const float*)d_in[11];
    const float* Whh3   = (const float*)d_in[12];
    const float* bih3   = (const float*)d_in[13];
    const float* bhh3   = (const float*)d_in[14];
    float* out = (float*)d_out;

    float *conv_p, *xg1_p;
    cudaGetSymbolAddress((void**)&conv_p, g_conv);
    cudaGetSymbolAddress((void**)&xg1_p,  g_xg1);

    cudaFuncSetAttribute(conv2_kernel,   cudaFuncAttributeMaxDynamicSharedMemorySize, CV2_SMEM_BYTES);
    cudaFuncSetAttribute(xg1_mma_kernel, cudaFuncAttributeMaxDynamicSharedMemorySize, XG_SMEM_BYTES);

    // 0) prepack conv weights -> g_wt
    prep_w_kernel<<<320, 256>>>(conv_w);

    // 1) conv (tf32 mma, cp.async pipelined) -> g_conv
    conv2_kernel<<<dim3(4, BATCH), 256, CV2_SMEM_BYTES>>>(x, conv_b);

    // 2) xg1 = seq @ Wih1^T + biases
    xg1_mma_kernel<<<MROWS / 128, 256, XG_SMEM_BYTES>>>(conv_p, Wih1, bih1, bhh1, xg1_p);

    // 3) fused LSTM1+2+3 -> d_out
    fused_lstm_kernel<<<BATCH, 128>>>(xg1_p, Whh1, Wih2, Whh2, bih2, bhh2,
                                      Wih3, Whh3, bih3, bhh3, out);

    (void)in_sizes; (void)n_in; (void)out_size;
}